// round 4
// baseline (speedup 1.0000x reference)
#include <cuda_runtime.h>
#include <cuda_bf16.h>
#include <cstdint>

// ---------------- problem sizes ----------------
#define TOKENS 8192
#define DMODEL 2048
#define DFF    8192

// ---------------- GEMM tiling ------------------
#define BM 128
#define BN 256
#define BK 128
#define STAGES 3
#define ROWB 144                        // 128B data + 16B pad: conflict-free ldmatrix
#define TILE_A (BM * ROWB)              // 18432 B
#define TILE_B (BN * ROWB)              // 36864 B
#define STAGE_BYTES (TILE_A + TILE_B)   // 55296 B
#define GEMM_SMEM (STAGES * STAGE_BYTES)// 165888 B

// ---------------- scratch (no allocations allowed) ----------------
__device__ int8_t g_xq [(size_t)TOKENS * DMODEL];
__device__ int8_t g_w1q[(size_t)DFF    * DMODEL];
__device__ int8_t g_w2q[(size_t)DMODEL * DFF];
__device__ int8_t g_hq [(size_t)TOKENS * DFF];
__device__ int    g_ha [(size_t)TOKENS * DFF];   // relu(acc1), exact s32
__device__ float  g_d1[TOKENS];
__device__ float  g_d2[TOKENS];
__device__ int    g_rowmax[TOKENS];
__device__ double g_part[2][1024];
__device__ float  g_gamma[2];

// ---------------- PTX helpers ----------------
__device__ __forceinline__ uint32_t smem_u32(const void* p) {
    uint32_t a;
    asm("{ .reg .u64 t; cvta.to.shared.u64 t, %1; cvt.u32.u64 %0, t; }" : "=r"(a) : "l"(p));
    return a;
}
#define CPA16(s, g) \
    asm volatile("cp.async.cg.shared.global [%0], [%1], 16;" :: "r"(s), "l"(g))
#define CP_COMMIT() asm volatile("cp.async.commit_group;" ::: "memory")
#define CP_WAIT1()  asm volatile("cp.async.wait_group 1;" ::: "memory")
#define LDSM4(r0, r1, r2, r3, addr) \
    asm volatile("ldmatrix.sync.aligned.m8n8.x4.shared.b16 {%0,%1,%2,%3}, [%4];" \
                 : "=r"(r0), "=r"(r1), "=r"(r2), "=r"(r3) : "r"(addr))
#define MMA_S8(c, a, b) \
    asm volatile("mma.sync.aligned.m16n8k32.row.col.s32.s8.s8.s32 " \
                 "{%0,%1,%2,%3}, {%4,%5,%6,%7}, {%8,%9}, {%0,%1,%2,%3};" \
                 : "+r"((c)[0]), "+r"((c)[1]), "+r"((c)[2]), "+r"((c)[3]) \
                 : "r"((a)[0]), "r"((a)[1]), "r"((a)[2]), "r"((a)[3]), \
                   "r"((b)[0]), "r"((b)[1]))

// ---------------- aux kernels ----------------
__global__ void k_absmean(const float* __restrict__ w1, const float* __restrict__ w2) {
    __shared__ double red[256];
    const int idx = blockIdx.y;
    const float* w = idx ? w2 : w1;
    const size_t n = (size_t)DFF * DMODEL;
    double s = 0.0;
    for (size_t i = (size_t)blockIdx.x * 256 + threadIdx.x; i < n; i += (size_t)gridDim.x * 256)
        s += (double)fabsf(w[i]);
    red[threadIdx.x] = s;
    __syncthreads();
    for (int o = 128; o > 0; o >>= 1) {
        if (threadIdx.x < o) red[threadIdx.x] += red[threadIdx.x + o];
        __syncthreads();
    }
    if (threadIdx.x == 0) g_part[idx][blockIdx.x] = red[0];
}

__global__ void k_finalize_gamma() {
    const double n = (double)DFF * DMODEL;
    for (int j = 0; j < 2; j++) {
        double s = 0.0;
        for (int i = 0; i < 1024; i++) s += g_part[j][i];
        g_gamma[j] = (float)(s / n) + 1e-5f;
    }
}

__global__ void k_quantize_w(const float* __restrict__ w, int idx) {
    int8_t* dst = idx ? g_w2q : g_w1q;
    const float g = g_gamma[idx];
    const float4* w4 = (const float4*)w;
    char4* d4 = (char4*)dst;
    const size_t n4 = (size_t)DFF * DMODEL / 4;
    for (size_t i = (size_t)blockIdx.x * blockDim.x + threadIdx.x; i < n4;
         i += (size_t)gridDim.x * blockDim.x) {
        float4 v = w4[i];
        float t0 = fminf(fmaxf(rintf(v.x / g), -1.f), 1.f);
        float t1 = fminf(fmaxf(rintf(v.y / g), -1.f), 1.f);
        float t2 = fminf(fmaxf(rintf(v.z / g), -1.f), 1.f);
        float t3 = fminf(fmaxf(rintf(v.w / g), -1.f), 1.f);
        d4[i] = make_char4((char)(int)t0, (char)(int)t1, (char)(int)t2, (char)(int)t3);
    }
}

__global__ void k_quantize_x(const float* __restrict__ x) {
    __shared__ float red[256];
    const int t = blockIdx.x;
    const float4* row = (const float4*)(x + (size_t)t * DMODEL);
    float m = 0.f;
    for (int i = threadIdx.x; i < DMODEL / 4; i += 256) {
        float4 v = row[i];
        m = fmaxf(m, fmaxf(fmaxf(fabsf(v.x), fabsf(v.y)), fmaxf(fabsf(v.z), fabsf(v.w))));
    }
    red[threadIdx.x] = m;
    __syncthreads();
    for (int o = 128; o > 0; o >>= 1) {
        if (threadIdx.x < o) red[threadIdx.x] = fmaxf(red[threadIdx.x], red[threadIdx.x + o]);
        __syncthreads();
    }
    const float s = 127.0f / fmaxf(red[0], 1e-5f);
    char4* dst = (char4*)(g_xq + (size_t)t * DMODEL);
    for (int i = threadIdx.x; i < DMODEL / 4; i += 256) {
        float4 v = row[i];
        float q0 = fminf(fmaxf(rintf(v.x * s), -128.f), 127.f);
        float q1 = fminf(fmaxf(rintf(v.y * s), -128.f), 127.f);
        float q2 = fminf(fmaxf(rintf(v.z * s), -128.f), 127.f);
        float q3 = fminf(fmaxf(rintf(v.w * s), -128.f), 127.f);
        dst[i] = make_char4((char)(int)q0, (char)(int)q1, (char)(int)q2, (char)(int)q3);
    }
    if (threadIdx.x == 0) {
        g_d1[t] = g_gamma[0] / s;
        g_rowmax[t] = 0;
    }
}

__global__ void k_quantize_h() {
    const int t = blockIdx.x;
    const float d1 = g_d1[t];
    const float hl = d1 * (float)g_rowmax[t];
    const float s2 = 127.0f / fmaxf(hl * hl, 1e-5f);
    const int4* src = (const int4*)(g_ha + (size_t)t * DFF);
    char4* dst = (char4*)(g_hq + (size_t)t * DFF);
    for (int i = threadIdx.x; i < DFF / 4; i += blockDim.x) {
        int4 v = src[i];
        float a0 = (float)v.x * d1, a1 = (float)v.y * d1;
        float a2 = (float)v.z * d1, a3 = (float)v.w * d1;
        float q0 = fminf(rintf(a0 * a0 * s2), 127.f);
        float q1 = fminf(rintf(a1 * a1 * s2), 127.f);
        float q2 = fminf(rintf(a2 * a2 * s2), 127.f);
        float q3 = fminf(rintf(a3 * a3 * s2), 127.f);
        dst[i] = make_char4((char)(int)q0, (char)(int)q1, (char)(int)q2, (char)(int)q3);
    }
    if (threadIdx.x == 0) g_d2[t] = g_gamma[1] / s2;
}

// ---------------- int8 tensor-core GEMM ----------------
// C[BM,BN] = A[M,K] (row-major s8) * B[N,K]^T (row-major s8), s32 accum.
// 8 warps in 2x4 grid, warp tile 64x64. 3-stage cp.async pipeline, BK=128.
// MODE 1: relu(acc) -> outI (s32) + atomicMax rowmax.  MODE 0: acc*d2[row] -> outF.
template<int MODE>
__global__ void __launch_bounds__(256, 1) k_gemm(
    const int8_t* __restrict__ A, const int8_t* __restrict__ B,
    int K, int ldo,
    int* __restrict__ outI, float* __restrict__ outF,
    int* __restrict__ rowmax, const float* __restrict__ d2)
{
    extern __shared__ char smem[];
    const uint32_t sbase = smem_u32(smem);
    const int t = threadIdx.x;
    const int wid = t >> 5, lane = t & 31;
    const int wm = wid >> 2, wn = wid & 3;          // 2 x 4 warp grid, 64x64 tiles
    const int mBase = blockIdx.y * BM, nBase = blockIdx.x * BN;
    const int kChunks = K / BK;

    int acc[4][8][4];
    #pragma unroll
    for (int i = 0; i < 4; i++)
        #pragma unroll
        for (int j = 0; j < 8; j++)
            #pragma unroll
            for (int r = 0; r < 4; r++) acc[i][j][r] = 0;

    // per-lane ldmatrix offsets (validated layout from passing R3 kernel)
    const int lrow = lane & 7;
    const uint32_t aOff = (uint32_t)((lrow + ((lane >> 3) & 1) * 8) * ROWB + (lane >> 4) * 16);
    const uint32_t bOff = (uint32_t)((lrow + (lane >> 4) * 8) * ROWB + ((lane >> 3) & 1) * 16);

    // stage loader: 256 threads, 16B each; A 4 row-blocks, B 8 row-blocks
    const int ldrow = t >> 3, ldch = t & 7;
    auto load_stage = [&](int kt, int slot) {
        const uint32_t sA = sbase + slot * STAGE_BYTES;
        const int k0 = kt * BK + ldch * 16;
        #pragma unroll
        for (int i = 0; i < 4; i++) {
            int row = ldrow + i * 32;
            CPA16(sA + row * ROWB + ldch * 16, A + (size_t)(mBase + row) * K + k0);
        }
        #pragma unroll
        for (int i = 0; i < 8; i++) {
            int row = ldrow + i * 32;
            CPA16(sA + TILE_A + row * ROWB + ldch * 16, B + (size_t)(nBase + row) * K + k0);
        }
        CP_COMMIT();
    };

    load_stage(0, 0);
    load_stage(1, 1);

    for (int kt = 0; kt < kChunks; kt++) {
        CP_WAIT1();
        __syncthreads();
        const int nk = kt + 2;
        if (nk < kChunks) load_stage(nk, nk % 3);
        else CP_COMMIT();                           // keep group count invariant

        const uint32_t sA = sbase + (kt % 3) * STAGE_BYTES;
        const uint32_t sB = sA + TILE_A;
        #pragma unroll
        for (int ks = 0; ks < 4; ks++) {            // four K=32 steps per BK=128
            uint32_t a[4][4], b[8][2];
            #pragma unroll
            for (int mi = 0; mi < 4; mi++)
                LDSM4(a[mi][0], a[mi][1], a[mi][2], a[mi][3],
                      sA + (wm * 64 + mi * 16) * ROWB + aOff + ks * 32);
            #pragma unroll
            for (int g = 0; g < 4; g++) {
                uint32_t r0, r1, r2, r3;
                LDSM4(r0, r1, r2, r3,
                      sB + (wn * 64 + g * 16) * ROWB + bOff + ks * 32);
                b[g * 2][0] = r0; b[g * 2][1] = r1;
                b[g * 2 + 1][0] = r2; b[g * 2 + 1][1] = r3;
            }
            #pragma unroll
            for (int mi = 0; mi < 4; mi++)
                #pragma unroll
                for (int ni = 0; ni < 8; ni++)
                    MMA_S8(acc[mi][ni], a[mi], b[ni]);
        }
    }

    // ---------------- epilogue ----------------
    #pragma unroll
    for (int mi = 0; mi < 4; mi++) {
        #pragma unroll
        for (int hf = 0; hf < 2; hf++) {
            const int row = mBase + wm * 64 + mi * 16 + hf * 8 + (lane >> 2);
            if (MODE == 1) {
                int rm = 0;
                #pragma unroll
                for (int ni = 0; ni < 8; ni++) {
                    int v0 = max(acc[mi][ni][hf * 2 + 0], 0);
                    int v1 = max(acc[mi][ni][hf * 2 + 1], 0);
                    rm = max(rm, max(v0, v1));
                    const int col = nBase + wn * 64 + ni * 8 + 2 * (lane & 3);
                    *(int2*)(outI + (size_t)row * ldo + col) = make_int2(v0, v1);
                }
                rm = max(rm, __shfl_xor_sync(0xffffffffu, rm, 1));
                rm = max(rm, __shfl_xor_sync(0xffffffffu, rm, 2));
                if ((lane & 3) == 0) atomicMax(&rowmax[row], rm);
            } else {
                const float s = d2[row];
                #pragma unroll
                for (int ni = 0; ni < 8; ni++) {
                    float v0 = (float)acc[mi][ni][hf * 2 + 0] * s;
                    float v1 = (float)acc[mi][ni][hf * 2 + 1] * s;
                    const int col = nBase + wn * 64 + ni * 8 + 2 * (lane & 3);
                    *(float2*)(outF + (size_t)row * ldo + col) = make_float2(v0, v1);
                }
            }
        }
    }
}

// ---------------- host ----------------
extern "C" void kernel_launch(void* const* d_in, const int* in_sizes, int n_in,
                              void* d_out, int out_size) {
    const float* x  = (const float*)d_in[0];
    const float* w1 = (const float*)d_in[1];
    const float* w2 = (const float*)d_in[2];
    float* out = (float*)d_out;

    void *p_xq, *p_w1q, *p_w2q, *p_hq, *p_ha, *p_d2, *p_rm;
    cudaGetSymbolAddress(&p_xq,  g_xq);
    cudaGetSymbolAddress(&p_w1q, g_w1q);
    cudaGetSymbolAddress(&p_w2q, g_w2q);
    cudaGetSymbolAddress(&p_hq,  g_hq);
    cudaGetSymbolAddress(&p_ha,  g_ha);
    cudaGetSymbolAddress(&p_d2,  g_d2);
    cudaGetSymbolAddress(&p_rm,  g_rowmax);

    cudaFuncSetAttribute(k_gemm<1>, cudaFuncAttributeMaxDynamicSharedMemorySize, GEMM_SMEM);
    cudaFuncSetAttribute(k_gemm<0>, cudaFuncAttributeMaxDynamicSharedMemorySize, GEMM_SMEM);

    // launch order chosen so ncu's -s 5 lands on gemm1 next profile
    k_absmean<<<dim3(1024, 2), 256>>>(w1, w2);      // 0
    k_finalize_gamma<<<1, 1>>>();                   // 1
    k_quantize_w<<<4096, 256>>>(w1, 0);             // 2
    k_quantize_w<<<4096, 256>>>(w2, 1);             // 3
    k_quantize_x<<<TOKENS, 256>>>(x);               // 4

    dim3 g1(DFF / BN, TOKENS / BM);                 // 32 x 64
    k_gemm<1><<<g1, 256, GEMM_SMEM>>>((const int8_t*)p_xq, (const int8_t*)p_w1q,   // 5
                                      DMODEL, DFF,
                                      (int*)p_ha, nullptr, (int*)p_rm, nullptr);

    k_quantize_h<<<TOKENS, 256>>>();                // 6

    dim3 g2(DMODEL / BN, TOKENS / BM);              // 8 x 64
    k_gemm<0><<<g2, 256, GEMM_SMEM>>>((const int8_t*)p_hq, (const int8_t*)p_w2q,   // 7
                                      DFF, DMODEL,
                                      nullptr, out, nullptr, (const float*)p_d2);
}

// round 5
// speedup vs baseline: 1.1461x; 1.1461x over previous
#include <cuda_runtime.h>
#include <cuda_bf16.h>
#include <cstdint>

// ---------------- problem sizes ----------------
#define TOKENS 8192
#define DMODEL 2048
#define DFF    8192

// ---------------- GEMM tiling (R3 shape, deeper pipeline) ----------------
#define BM 128
#define BN 128
#define BK 64
#define STAGES 5
#define ROWB 80                         // 64B data + 16B pad: conflict-free ldmatrix
#define TILEB (128 * ROWB)              // 10240 B per operand tile
#define STAGE_BYTES (2 * TILEB)         // 20480 B
#define GEMM_SMEM (STAGES * STAGE_BYTES)// 102400 B -> 2 CTAs/SM

// ---------------- scratch (no allocations allowed) ----------------
__device__ int8_t g_xq [(size_t)TOKENS * DMODEL];
__device__ int8_t g_w1q[(size_t)DFF    * DMODEL];
__device__ int8_t g_w2q[(size_t)DMODEL * DFF];
__device__ int8_t g_hq [(size_t)TOKENS * DFF];
__device__ int    g_ha [(size_t)TOKENS * DFF];   // relu(acc1), exact s32
__device__ float  g_sx[TOKENS];                  // 127/absmax per token
__device__ float  g_d2[TOKENS];
__device__ int    g_rowmax[TOKENS];
__device__ double g_sum[2];                      // atomic |w| accumulators

// ---------------- PTX helpers ----------------
__device__ __forceinline__ uint32_t smem_u32(const void* p) {
    uint32_t a;
    asm("{ .reg .u64 t; cvta.to.shared.u64 t, %1; cvt.u32.u64 %0, t; }" : "=r"(a) : "l"(p));
    return a;
}
#define CPA16(s, g) \
    asm volatile("cp.async.cg.shared.global [%0], [%1], 16;" :: "r"(s), "l"(g))
#define CP_COMMIT() asm volatile("cp.async.commit_group;" ::: "memory")
#define CP_WAIT3()  asm volatile("cp.async.wait_group 3;" ::: "memory")
#define LDSM4(r0, r1, r2, r3, addr) \
    asm volatile("ldmatrix.sync.aligned.m8n8.x4.shared.b16 {%0,%1,%2,%3}, [%4];" \
                 : "=r"(r0), "=r"(r1), "=r"(r2), "=r"(r3) : "r"(addr))
#define MMA_S8(c, a, b) \
    asm volatile("mma.sync.aligned.m16n8k32.row.col.s32.s8.s8.s32 " \
                 "{%0,%1,%2,%3}, {%4,%5,%6,%7}, {%8,%9}, {%0,%1,%2,%3};" \
                 : "+r"((c)[0]), "+r"((c)[1]), "+r"((c)[2]), "+r"((c)[3]) \
                 : "r"((a)[0]), "r"((a)[1]), "r"((a)[2]), "r"((a)[3]), \
                   "r"((b)[0]), "r"((b)[1]))

// ---------------- aux kernels ----------------
// launch 0: quantize x, reset rowmax, zero gamma accumulators
__global__ void k_quantize_x(const float* __restrict__ x) {
    __shared__ float red[256];
    const int t = blockIdx.x;
    if (t == 0 && threadIdx.x == 0) { g_sum[0] = 0.0; g_sum[1] = 0.0; }
    const float4* row = (const float4*)(x + (size_t)t * DMODEL);
    float m = 0.f;
    for (int i = threadIdx.x; i < DMODEL / 4; i += 256) {
        float4 v = row[i];
        m = fmaxf(m, fmaxf(fmaxf(fabsf(v.x), fabsf(v.y)), fmaxf(fabsf(v.z), fabsf(v.w))));
    }
    red[threadIdx.x] = m;
    __syncthreads();
    for (int o = 128; o > 0; o >>= 1) {
        if (threadIdx.x < o) red[threadIdx.x] = fmaxf(red[threadIdx.x], red[threadIdx.x + o]);
        __syncthreads();
    }
    const float s = 127.0f / fmaxf(red[0], 1e-5f);
    char4* dst = (char4*)(g_xq + (size_t)t * DMODEL);
    for (int i = threadIdx.x; i < DMODEL / 4; i += 256) {
        float4 v = row[i];
        float q0 = fminf(fmaxf(rintf(v.x * s), -128.f), 127.f);
        float q1 = fminf(fmaxf(rintf(v.y * s), -128.f), 127.f);
        float q2 = fminf(fmaxf(rintf(v.z * s), -128.f), 127.f);
        float q3 = fminf(fmaxf(rintf(v.w * s), -128.f), 127.f);
        dst[i] = make_char4((char)(int)q0, (char)(int)q1, (char)(int)q2, (char)(int)q3);
    }
    if (threadIdx.x == 0) { g_sx[t] = s; g_rowmax[t] = 0; }
}

// launch 1: |w| sums for both weights (atomicAdd; 1e-16-relative jitter is harmless)
__global__ void k_absmean(const float* __restrict__ w1, const float* __restrict__ w2) {
    __shared__ double red[256];
    const int idx = blockIdx.y;
    const float* w = idx ? w2 : w1;
    const size_t n = (size_t)DFF * DMODEL;
    double s = 0.0;
    for (size_t i = (size_t)blockIdx.x * 256 + threadIdx.x; i < n; i += (size_t)gridDim.x * 256)
        s += (double)fabsf(w[i]);
    red[threadIdx.x] = s;
    __syncthreads();
    for (int o = 128; o > 0; o >>= 1) {
        if (threadIdx.x < o) red[threadIdx.x] += red[threadIdx.x + o];
        __syncthreads();
    }
    if (threadIdx.x == 0) atomicAdd(&g_sum[idx], red[0]);
}

// launches 2,4: ternarize weights (gamma finalized inline)
__global__ void k_quantize_w(const float* __restrict__ w, int idx) {
    int8_t* dst = idx ? g_w2q : g_w1q;
    const double n = (double)DFF * DMODEL;
    const float g = (float)(g_sum[idx] / n) + 1e-5f;
    const float4* w4 = (const float4*)w;
    char4* d4 = (char4*)dst;
    const size_t n4 = (size_t)DFF * DMODEL / 4;
    for (size_t i = (size_t)blockIdx.x * blockDim.x + threadIdx.x; i < n4;
         i += (size_t)gridDim.x * blockDim.x) {
        float4 v = w4[i];
        float t0 = fminf(fmaxf(rintf(v.x / g), -1.f), 1.f);
        float t1 = fminf(fmaxf(rintf(v.y / g), -1.f), 1.f);
        float t2 = fminf(fmaxf(rintf(v.z / g), -1.f), 1.f);
        float t3 = fminf(fmaxf(rintf(v.w / g), -1.f), 1.f);
        d4[i] = make_char4((char)(int)t0, (char)(int)t1, (char)(int)t2, (char)(int)t3);
    }
}

// launch 5: requantize h (computes d1, d2 inline)
__global__ void k_quantize_h() {
    const int t = blockIdx.x;
    const double n = (double)DFF * DMODEL;
    const float gamma0 = (float)(g_sum[0] / n) + 1e-5f;
    const float gamma1 = (float)(g_sum[1] / n) + 1e-5f;
    const float d1 = gamma0 / g_sx[t];
    const float hl = d1 * (float)g_rowmax[t];
    const float s2 = 127.0f / fmaxf(hl * hl, 1e-5f);
    const int4* src = (const int4*)(g_ha + (size_t)t * DFF);
    char4* dst = (char4*)(g_hq + (size_t)t * DFF);
    for (int i = threadIdx.x; i < DFF / 4; i += blockDim.x) {
        int4 v = src[i];
        float a0 = (float)v.x * d1, a1 = (float)v.y * d1;
        float a2 = (float)v.z * d1, a3 = (float)v.w * d1;
        float q0 = fminf(rintf(a0 * a0 * s2), 127.f);
        float q1 = fminf(rintf(a1 * a1 * s2), 127.f);
        float q2 = fminf(rintf(a2 * a2 * s2), 127.f);
        float q3 = fminf(rintf(a3 * a3 * s2), 127.f);
        dst[i] = make_char4((char)(int)q0, (char)(int)q1, (char)(int)q2, (char)(int)q3);
    }
    if (threadIdx.x == 0) g_d2[t] = gamma1 / s2;
}

// ---------------- int8 tensor-core GEMM ----------------
// C[BM,BN] = A[M,K] (row-major s8) * B[N,K]^T (row-major s8), s32 accum.
// 8 warps in 2x4 grid, warp tile 64x32. 5-stage cp.async pipeline, BK=64.
// MODE 1: relu(acc) -> outI (s32) + atomicMax rowmax.  MODE 0: acc*d2[row] -> outF.
template<int MODE>
__global__ void __launch_bounds__(256, 2) k_gemm(
    const int8_t* __restrict__ A, const int8_t* __restrict__ B,
    int K, int ldo,
    int* __restrict__ outI, float* __restrict__ outF,
    int* __restrict__ rowmax, const float* __restrict__ d2)
{
    extern __shared__ char smem[];
    const uint32_t sbase = smem_u32(smem);
    const int t = threadIdx.x;
    const int wid = t >> 5, lane = t & 31;
    const int wm = wid >> 2, wn = wid & 3;          // 2 x 4 warp grid
    const int mBase = blockIdx.y * BM, nBase = blockIdx.x * BN;
    const int kChunks = K / BK;

    int acc[4][4][4];
    #pragma unroll
    for (int i = 0; i < 4; i++)
        #pragma unroll
        for (int j = 0; j < 4; j++)
            #pragma unroll
            for (int r = 0; r < 4; r++) acc[i][j][r] = 0;

    const int lrow = lane & 7;
    const uint32_t aOff = (uint32_t)((lrow + ((lane >> 3) & 1) * 8) * ROWB + (lane >> 4) * 16);
    const uint32_t bOff = (uint32_t)((lrow + (lane >> 4) * 8) * ROWB + ((lane >> 3) & 1) * 16);

    const int ldrow = t >> 2, ldch = t & 3;         // 256 threads: rows 0..63 x 4 chunks
    auto load_stage = [&](int kt, int slot) {
        const uint32_t sA = sbase + slot * STAGE_BYTES;
        const int k0 = kt * BK + ldch * 16;
        #pragma unroll
        for (int i = 0; i < 2; i++) {
            int row = ldrow + i * 64;
            CPA16(sA + row * ROWB + ldch * 16,
                  A + (size_t)(mBase + row) * K + k0);
            CPA16(sA + TILEB + row * ROWB + ldch * 16,
                  B + (size_t)(nBase + row) * K + k0);
        }
        CP_COMMIT();
    };

    load_stage(0, 0);
    load_stage(1, 1);
    load_stage(2, 2);
    load_stage(3, 3);

    for (int kt = 0; kt < kChunks; kt++) {
        CP_WAIT3();
        __syncthreads();
        const int nk = kt + 4;
        if (nk < kChunks) load_stage(nk, nk % STAGES);
        else CP_COMMIT();                           // keep group count invariant

        const uint32_t sA = sbase + (kt % STAGES) * STAGE_BYTES;
        const uint32_t sB = sA + TILEB;
        #pragma unroll
        for (int ks = 0; ks < 2; ks++) {            // two K=32 steps per BK=64
            uint32_t a[4][4], b[4][2];
            #pragma unroll
            for (int mi = 0; mi < 4; mi++)
                LDSM4(a[mi][0], a[mi][1], a[mi][2], a[mi][3],
                      sA + (wm * 64 + mi * 16) * ROWB + aOff + ks * 32);
            #pragma unroll
            for (int hf = 0; hf < 2; hf++) {
                uint32_t r0, r1, r2, r3;
                LDSM4(r0, r1, r2, r3,
                      sB + (wn * 32 + hf * 16) * ROWB + bOff + ks * 32);
                b[hf * 2][0] = r0; b[hf * 2][1] = r1;
                b[hf * 2 + 1][0] = r2; b[hf * 2 + 1][1] = r3;
            }
            #pragma unroll
            for (int mi = 0; mi < 4; mi++)
                #pragma unroll
                for (int ni = 0; ni < 4; ni++)
                    MMA_S8(acc[mi][ni], a[mi], b[ni]);
        }
    }

    // ---------------- epilogue ----------------
    #pragma unroll
    for (int mi = 0; mi < 4; mi++) {
        #pragma unroll
        for (int hf = 0; hf < 2; hf++) {
            const int row = mBase + wm * 64 + mi * 16 + hf * 8 + (lane >> 2);
            if (MODE == 1) {
                int rm = 0;
                #pragma unroll
                for (int ni = 0; ni < 4; ni++) {
                    int v0 = max(acc[mi][ni][hf * 2 + 0], 0);
                    int v1 = max(acc[mi][ni][hf * 2 + 1], 0);
                    rm = max(rm, max(v0, v1));
                    const int col = nBase + wn * 32 + ni * 8 + 2 * (lane & 3);
                    *(int2*)(outI + (size_t)row * ldo + col) = make_int2(v0, v1);
                }
                rm = max(rm, __shfl_xor_sync(0xffffffffu, rm, 1));
                rm = max(rm, __shfl_xor_sync(0xffffffffu, rm, 2));
                if ((lane & 3) == 0) atomicMax(&rowmax[row], rm);
            } else {
                const float s = d2[row];
                #pragma unroll
                for (int ni = 0; ni < 4; ni++) {
                    float v0 = (float)acc[mi][ni][hf * 2 + 0] * s;
                    float v1 = (float)acc[mi][ni][hf * 2 + 1] * s;
                    const int col = nBase + wn * 32 + ni * 8 + 2 * (lane & 3);
                    *(float2*)(outF + (size_t)row * ldo + col) = make_float2(v0, v1);
                }
            }
        }
    }
}

// ---------------- host ----------------
extern "C" void kernel_launch(void* const* d_in, const int* in_sizes, int n_in,
                              void* d_out, int out_size) {
    const float* x  = (const float*)d_in[0];
    const float* w1 = (const float*)d_in[1];
    const float* w2 = (const float*)d_in[2];
    float* out = (float*)d_out;

    void *p_xq, *p_w1q, *p_w2q, *p_hq, *p_ha, *p_d2, *p_rm;
    cudaGetSymbolAddress(&p_xq,  g_xq);
    cudaGetSymbolAddress(&p_w1q, g_w1q);
    cudaGetSymbolAddress(&p_w2q, g_w2q);
    cudaGetSymbolAddress(&p_hq,  g_hq);
    cudaGetSymbolAddress(&p_ha,  g_ha);
    cudaGetSymbolAddress(&p_d2,  g_d2);
    cudaGetSymbolAddress(&p_rm,  g_rowmax);

    cudaFuncSetAttribute(k_gemm<1>, cudaFuncAttributeMaxDynamicSharedMemorySize, GEMM_SMEM);
    cudaFuncSetAttribute(k_gemm<0>, cudaFuncAttributeMaxDynamicSharedMemorySize, GEMM_SMEM);

    // order: gemm1 is my launch idx 3 -> overall #5 given 2 harness pre-launches
    k_quantize_x<<<TOKENS, 256>>>(x);                    // 0
    k_absmean<<<dim3(1024, 2), 256>>>(w1, w2);           // 1
    k_quantize_w<<<4096, 256>>>(w1, 0);                  // 2

    dim3 g1(DFF / BN, TOKENS / BM);                      // 3: 64 x 64
    k_gemm<1><<<g1, 256, GEMM_SMEM>>>((const int8_t*)p_xq, (const int8_t*)p_w1q,
                                      DMODEL, DFF,
                                      (int*)p_ha, nullptr, (int*)p_rm, nullptr);

    k_quantize_w<<<4096, 256>>>(w2, 1);                  // 4
    k_quantize_h<<<TOKENS, 256>>>();                     // 5

    dim3 g2(DMODEL / BN, TOKENS / BM);                   // 6: 16 x 64
    k_gemm<0><<<g2, 256, GEMM_SMEM>>>((const int8_t*)p_hq, (const int8_t*)p_w2q,
                                      DFF, DMODEL,
                                      nullptr, out, nullptr, (const float*)p_d2);
}